// round 2
// baseline (speedup 1.0000x reference)
#include <cuda_runtime.h>
#include <math.h>
#include <stdint.h>

#define EPSF 1e-5f
#define NN 100000
#define NE 3200000
#define D 256

// ---------------- scratch (static __device__; no allocations allowed) -------
__device__ float g_htan[(size_t)NN * D];   // log-mapped features
__device__ int   g_cnt[NN];
__device__ int   g_rowptr[NN + 1];
__device__ int   g_cursor[NN];
__device__ int   g_scols[NE];
__device__ float g_svals[NE];
__device__ float g_bhyp[D];
__device__ float g_c, g_sqrtc, g_bb;

// ---------------- helpers ---------------------------------------------------
__device__ __forceinline__ float warp_sum(float v) {
#pragma unroll
    for (int o = 16; o > 0; o >>= 1) v += __shfl_xor_sync(0xffffffffu, v, o);
    return v;
}

// ---------------- prep: c = softplus(c_theta), b_hyp = exp_0(bias) ----------
__global__ void prep_kernel(const float* __restrict__ bias,
                            const float* __restrict__ c_theta) {
    __shared__ float red[D];
    __shared__ float s_c, s_sc;
    int t = threadIdx.x;
    if (t == 0) {
        float c = log1pf(expf(c_theta[0]));
        s_c = c;
        s_sc = sqrtf(c);
    }
    __syncthreads();
    float sc = s_sc;
    float bv = bias[t];
    red[t] = bv * bv;
#pragma unroll
    for (int o = 128; o > 0; o >>= 1) {
        __syncthreads();
        if (t < o) red[t] += red[t + o];
    }
    __syncthreads();
    float bn2 = red[0];
    __syncthreads();
    float n = fmaxf(sqrtf(bn2), EPSF);
    float tt = tanhf(sc * n) / (sc * n);
    float bh = tt * bv;
    g_bhyp[t] = bh;
    red[t] = bh * bh;
#pragma unroll
    for (int o = 128; o > 0; o >>= 1) {
        __syncthreads();
        if (t < o) red[t] += red[t + o];
    }
    __syncthreads();
    if (t == 0) {
        g_c = s_c;
        g_sqrtc = s_sc;
        g_bb = red[0];
    }
}

// ---------------- CSR build --------------------------------------------------
__global__ void zero_cnt_kernel(int n) {
    int i = blockIdx.x * blockDim.x + threadIdx.x;
    if (i < n) g_cnt[i] = 0;
}

__global__ void hist_kernel(const int* __restrict__ rows, int e) {
    int i = blockIdx.x * blockDim.x + threadIdx.x;
    if (i < e) atomicAdd(&g_cnt[rows[i]], 1);
}

__global__ void scan_kernel(int n) {
    __shared__ int ss[1024];
    int t = threadIdx.x;
    int per = (n + 1023) >> 10;
    int start = t * per;
    int stop = min(start + per, n);
    int local = 0;
    for (int i = start; i < stop; i++) local += g_cnt[i];
    ss[t] = local;
    __syncthreads();
#pragma unroll
    for (int o = 1; o < 1024; o <<= 1) {
        int v = (t >= o) ? ss[t - o] : 0;
        __syncthreads();
        ss[t] += v;
        __syncthreads();
    }
    int run = ss[t] - local;  // exclusive prefix for this chunk
    for (int i = start; i < stop; i++) {
        g_rowptr[i] = run;
        g_cursor[i] = run;
        run += g_cnt[i];
    }
    if (t == 1023) g_rowptr[n] = ss[1023];
}

__global__ void scatter_kernel(const int* __restrict__ rows,
                               const int* __restrict__ cols,
                               const float* __restrict__ vals, int e) {
    int i = blockIdx.x * blockDim.x + threadIdx.x;
    if (i < e) {
        int r = rows[i];
        int p = atomicAdd(&g_cursor[r], 1);
        g_scols[p] = cols[i];
        g_svals[p] = vals[i];
    }
}

// ---------------- fused GEMM (64x256 tile) + hyperbolic pointwise -----------
// Block: 256 threads. warp ty = tid>>5 owns rows [row0+ty*8, +8); lane tx owns
// cols [tx*8, tx*8+8). After the GEMM mainloop each warp holds 8 complete
// rows of z in registers -> do exp_map/mobius/project/log_map in-register
// with warp reductions and write g_htan directly (z never touches HBM).
__global__ void __launch_bounds__(256)
gemm_fused_kernel(const float* __restrict__ X, const float* __restrict__ W,
                  int M) {
    __shared__ float As[8][64];
    __shared__ float Bs[8][256];
    int tid = threadIdx.x;
    int row0 = blockIdx.x * 64;
    int ty = tid >> 5, tx = tid & 31;

    int aRow = tid >> 1, aCol = (tid & 1) * 4;   // tid<128 loads A
    int bRow = tid >> 5, bCol = (tid & 31) * 8;  // every thread loads 2xfloat4 of B

    float acc[8][8];
#pragma unroll
    for (int i = 0; i < 8; i++)
#pragma unroll
        for (int j = 0; j < 8; j++) acc[i][j] = 0.f;

    for (int k0 = 0; k0 < 256; k0 += 8) {
        if (tid < 128) {
            float4 av = make_float4(0.f, 0.f, 0.f, 0.f);
            int gr = row0 + aRow;
            if (gr < M) av = *(const float4*)(X + (size_t)gr * 256 + k0 + aCol);
            As[aCol + 0][aRow] = av.x;
            As[aCol + 1][aRow] = av.y;
            As[aCol + 2][aRow] = av.z;
            As[aCol + 3][aRow] = av.w;
        }
        const float* wp = W + (size_t)(k0 + bRow) * 256 + bCol;
        *(float4*)(&Bs[bRow][bCol]) = *(const float4*)(wp);
        *(float4*)(&Bs[bRow][bCol + 4]) = *(const float4*)(wp + 4);
        __syncthreads();
#pragma unroll
        for (int k = 0; k < 8; k++) {
            float ra[8], rb[8];
            *(float4*)(ra) = *(const float4*)(&As[k][ty * 8]);
            *(float4*)(ra + 4) = *(const float4*)(&As[k][ty * 8 + 4]);
            *(float4*)(rb) = *(const float4*)(&Bs[k][tx * 8]);
            *(float4*)(rb + 4) = *(const float4*)(&Bs[k][tx * 8 + 4]);
#pragma unroll
            for (int i = 0; i < 8; i++)
#pragma unroll
                for (int j = 0; j < 8; j++)
                    acc[i][j] = fmaf(ra[i], rb[j], acc[i][j]);
        }
        __syncthreads();
    }

    // ---- fused pointwise: rows row0+ty*8+i, cols tx*8+j ----
    float c = g_c, sc = g_sqrtc, bb = g_bb;
    float bh[8];
    *(float4*)(bh) = *(const float4*)(g_bhyp + tx * 8);
    *(float4*)(bh + 4) = *(const float4*)(g_bhyp + tx * 8 + 4);

#pragma unroll
    for (int i = 0; i < 8; i++) {
        int gr = row0 + ty * 8 + i;
        float zz = 0.f, zb = 0.f;
#pragma unroll
        for (int j = 0; j < 8; j++) {
            zz = fmaf(acc[i][j], acc[i][j], zz);
            zb = fmaf(acc[i][j], bh[j], zb);
        }
        zz = warp_sum(zz);
        zb = warp_sum(zb);

        float n1 = fmaxf(sqrtf(zz), EPSF);
        float tt = tanhf(sc * n1) / (sc * n1);  // z_hyp = tt * z
        float aa = tt * tt * zz;                // ||z_hyp||^2
        float ab = tt * zb;                     // <z_hyp, b_hyp>

        float common = 1.f + 2.f * c * ab;
        float den = fmaxf(common + c * c * aa * bb, EPSF);
        float ca = (common + c * bb) * tt / den;  // coeff on z
        float cb = (1.f - c * aa) / den;          // coeff on b_hyp

        float h[8];
        float hh = 0.f;
#pragma unroll
        for (int j = 0; j < 8; j++) {
            h[j] = fmaf(ca, acc[i][j], cb * bh[j]);
            hh = fmaf(h[j], h[j], hh);
        }
        hh = warp_sum(hh);

        float nh = fmaxf(sqrtf(hh), EPSF);
        float maxn = (1.f - EPSF) / sc;
        float s = (nh > maxn) ? (maxn / nh) : 1.f;  // projection scale
        float n2 = fmaxf(nh * s, EPSF);
        float arg = fminf(sc * n2, 1.f - EPSF);
        float f = s * atanhf(arg) / (sc * n2);

        if (gr < M) {
            float* hp = g_htan + (size_t)gr * 256 + tx * 8;
            *(float4*)(hp) =
                make_float4(f * h[0], f * h[1], f * h[2], f * h[3]);
            *(float4*)(hp + 4) =
                make_float4(f * h[4], f * h[5], f * h[6], f * h[7]);
        }
    }
}

// ---------------- SpMM + ReLU (warp per row, lane owns 8 cols) --------------
__global__ void __launch_bounds__(256)
spmm_kernel(float* __restrict__ out, int n) {
    int warp = (blockIdx.x * blockDim.x + threadIdx.x) >> 5;
    int lane = threadIdx.x & 31;
    if (warp >= n) return;
    int start = g_rowptr[warp];
    int end = g_rowptr[warp + 1];

    float4 a0 = make_float4(0.f, 0.f, 0.f, 0.f);
    float4 a1 = make_float4(0.f, 0.f, 0.f, 0.f);

    for (int e0 = start; e0 < end; e0 += 32) {
        int e = e0 + lane;
        int cc = 0;
        float vv = 0.f;
        if (e < end) {
            cc = g_scols[e];
            vv = g_svals[e];
        }
        int m = min(32, end - e0);
        for (int j = 0; j < m; j++) {
            int cj = __shfl_sync(0xffffffffu, cc, j);
            float vj = __shfl_sync(0xffffffffu, vv, j);
            const float4* hp =
                (const float4*)(g_htan + (size_t)cj * 256 + lane * 8);
            float4 h0 = __ldg(hp);
            float4 h1 = __ldg(hp + 1);
            a0.x = fmaf(vj, h0.x, a0.x);
            a0.y = fmaf(vj, h0.y, a0.y);
            a0.z = fmaf(vj, h0.z, a0.z);
            a0.w = fmaf(vj, h0.w, a0.w);
            a1.x = fmaf(vj, h1.x, a1.x);
            a1.y = fmaf(vj, h1.y, a1.y);
            a1.z = fmaf(vj, h1.z, a1.z);
            a1.w = fmaf(vj, h1.w, a1.w);
        }
    }
    a0.x = fmaxf(a0.x, 0.f); a0.y = fmaxf(a0.y, 0.f);
    a0.z = fmaxf(a0.z, 0.f); a0.w = fmaxf(a0.w, 0.f);
    a1.x = fmaxf(a1.x, 0.f); a1.y = fmaxf(a1.y, 0.f);
    a1.z = fmaxf(a1.z, 0.f); a1.w = fmaxf(a1.w, 0.f);
    float4* op = (float4*)(out + (size_t)warp * 256 + lane * 8);
    op[0] = a0;
    op[1] = a1;
}

// ---------------- launch -----------------------------------------------------
extern "C" void kernel_launch(void* const* d_in, const int* in_sizes, int n_in,
                              void* d_out, int out_size) {
    const float* x      = (const float*)d_in[0];
    const int*   arows  = (const int*)d_in[1];
    const int*   acols  = (const int*)d_in[2];
    const float* avals  = (const float*)d_in[3];
    const float* W      = (const float*)d_in[4];
    const float* bias   = (const float*)d_in[5];
    const float* ctheta = (const float*)d_in[6];
    float* out = (float*)d_out;

    int M = in_sizes[0] / D;
    int E = in_sizes[1];
    if (M > NN) M = NN;
    if (E > NE) E = NE;

    prep_kernel<<<1, D>>>(bias, ctheta);
    zero_cnt_kernel<<<(M + 255) / 256, 256>>>(M);
    hist_kernel<<<(E + 255) / 256, 256>>>(arows, E);
    scan_kernel<<<1, 1024>>>(M);
    scatter_kernel<<<(E + 255) / 256, 256>>>(arows, acols, avals, E);
    gemm_fused_kernel<<<(M + 63) / 64, 256>>>(x, W, M);
    spmm_kernel<<<(M + 7) / 8, 256>>>(out, M);
}

// round 4
// speedup vs baseline: 1.2047x; 1.2047x over previous
#include <cuda_runtime.h>
#include <math.h>
#include <stdint.h>

#define EPSF 1e-5f
#define NN 100000
#define NE 3200000
#define D 256
#define SCAN_B 1024
#define NBLK ((NN + SCAN_B - 1) / SCAN_B)   // 98

// ---------------- scratch (static __device__; no allocations allowed) -------
__device__ float g_htan[(size_t)NN * D];   // log-mapped features
__device__ int   g_cnt[NN];
__device__ int   g_rowptr[NN + 1];
__device__ int   g_cursor[NN];
__device__ int   g_scols[NE];
__device__ float g_svals[NE];
__device__ int   g_bsum[NBLK];
__device__ int   g_boff[NBLK];
__device__ int   g_total;
__device__ float g_bhyp[D];
__device__ float g_c, g_sqrtc, g_bb;

// ---------------- helpers ---------------------------------------------------
__device__ __forceinline__ float warp_sum(float v) {
#pragma unroll
    for (int o = 16; o > 0; o >>= 1) v += __shfl_xor_sync(0xffffffffu, v, o);
    return v;
}

// ---------------- prep: c = softplus(c_theta), b_hyp = exp_0(bias) ----------
__global__ void prep_kernel(const float* __restrict__ bias,
                            const float* __restrict__ c_theta) {
    __shared__ float red[D];
    __shared__ float s_c, s_sc;
    int t = threadIdx.x;
    if (t == 0) {
        float c = log1pf(expf(c_theta[0]));
        s_c = c;
        s_sc = sqrtf(c);
    }
    __syncthreads();
    float sc = s_sc;
    float bv = bias[t];
    red[t] = bv * bv;
#pragma unroll
    for (int o = 128; o > 0; o >>= 1) {
        __syncthreads();
        if (t < o) red[t] += red[t + o];
    }
    __syncthreads();
    float bn2 = red[0];
    __syncthreads();
    float n = fmaxf(sqrtf(bn2), EPSF);
    float tt = tanhf(sc * n) / (sc * n);
    float bh = tt * bv;
    g_bhyp[t] = bh;
    red[t] = bh * bh;
#pragma unroll
    for (int o = 128; o > 0; o >>= 1) {
        __syncthreads();
        if (t < o) red[t] += red[t + o];
    }
    __syncthreads();
    if (t == 0) {
        g_c = s_c;
        g_sqrtc = s_sc;
        g_bb = red[0];
    }
}

// ---------------- CSR build --------------------------------------------------
__global__ void zero_cnt_kernel(int n) {
    int i = blockIdx.x * blockDim.x + threadIdx.x;
    if (i < n) g_cnt[i] = 0;
}

__global__ void hist_kernel(const int* __restrict__ rows, int e) {
    int i = blockIdx.x * blockDim.x + threadIdx.x;
    if (i < e) atomicAdd(&g_cnt[rows[i]], 1);
}

// pass 1: per-block scan of 1024 counts; exclusive partials -> g_rowptr,
// block total -> g_bsum
__global__ void __launch_bounds__(SCAN_B)
scan_block_kernel(int n) {
    __shared__ int ss[SCAN_B];
    int t = threadIdx.x;
    int i = blockIdx.x * SCAN_B + t;
    int v = (i < n) ? g_cnt[i] : 0;
    ss[t] = v;
    __syncthreads();
#pragma unroll
    for (int o = 1; o < SCAN_B; o <<= 1) {
        int u = (t >= o) ? ss[t - o] : 0;
        __syncthreads();
        ss[t] += u;
        __syncthreads();
    }
    if (i < n) g_rowptr[i] = ss[t] - v;  // exclusive, without block offset
    if (t == SCAN_B - 1) g_bsum[blockIdx.x] = ss[t];
}

// pass 2: exclusive scan of block sums (NBLK <= 128)
__global__ void scan_bsum_kernel(int nb) {
    __shared__ int ss[128];
    int t = threadIdx.x;
    int v = (t < nb) ? g_bsum[t] : 0;
    ss[t] = v;
    __syncthreads();
#pragma unroll
    for (int o = 1; o < 128; o <<= 1) {
        int u = (t >= o) ? ss[t - o] : 0;
        __syncthreads();
        ss[t] += u;
        __syncthreads();
    }
    if (t < nb) g_boff[t] = ss[t] - v;
    if (t == 127) g_total = ss[127];
}

// pass 3: add block offsets, init cursors, set rowptr[n]
__global__ void scan_add_kernel(int n) {
    int i = blockIdx.x * blockDim.x + threadIdx.x;
    if (i < n) {
        int r = g_rowptr[i] + g_boff[i >> 10];
        g_rowptr[i] = r;
        g_cursor[i] = r;
    }
    if (i == 0) g_rowptr[n] = g_total;
}

__global__ void scatter_kernel(const int* __restrict__ rows,
                               const int* __restrict__ cols,
                               const float* __restrict__ vals, int e) {
    int i = blockIdx.x * blockDim.x + threadIdx.x;
    if (i < e) {
        int r = rows[i];
        int p = atomicAdd(&g_cursor[r], 1);
        g_scols[p] = cols[i];
        g_svals[p] = vals[i];
    }
}

// ---------------- fused GEMM (64x256 tile) + hyperbolic pointwise -----------
__global__ void __launch_bounds__(256)
gemm_fused_kernel(const float* __restrict__ X, const float* __restrict__ W,
                  int M) {
    __shared__ float As[8][64];
    __shared__ float Bs[8][256];
    int tid = threadIdx.x;
    int row0 = blockIdx.x * 64;
    int ty = tid >> 5, tx = tid & 31;

    int aRow = tid >> 1, aCol = (tid & 1) * 4;   // tid<128 loads A
    int bRow = tid >> 5, bCol = (tid & 31) * 8;

    float acc[8][8];
#pragma unroll
    for (int i = 0; i < 8; i++)
#pragma unroll
        for (int j = 0; j < 8; j++) acc[i][j] = 0.f;

    for (int k0 = 0; k0 < 256; k0 += 8) {
        if (tid < 128) {
            float4 av = make_float4(0.f, 0.f, 0.f, 0.f);
            int gr = row0 + aRow;
            if (gr < M) av = *(const float4*)(X + (size_t)gr * 256 + k0 + aCol);
            As[aCol + 0][aRow] = av.x;
            As[aCol + 1][aRow] = av.y;
            As[aCol + 2][aRow] = av.z;
            As[aCol + 3][aRow] = av.w;
        }
        const float* wp = W + (size_t)(k0 + bRow) * 256 + bCol;
        *(float4*)(&Bs[bRow][bCol]) = *(const float4*)(wp);
        *(float4*)(&Bs[bRow][bCol + 4]) = *(const float4*)(wp + 4);
        __syncthreads();
#pragma unroll
        for (int k = 0; k < 8; k++) {
            float ra[8], rb[8];
            *(float4*)(ra) = *(const float4*)(&As[k][ty * 8]);
            *(float4*)(ra + 4) = *(const float4*)(&As[k][ty * 8 + 4]);
            *(float4*)(rb) = *(const float4*)(&Bs[k][tx * 8]);
            *(float4*)(rb + 4) = *(const float4*)(&Bs[k][tx * 8 + 4]);
#pragma unroll
            for (int i = 0; i < 8; i++)
#pragma unroll
                for (int j = 0; j < 8; j++)
                    acc[i][j] = fmaf(ra[i], rb[j], acc[i][j]);
        }
        __syncthreads();
    }

    // ---- fused pointwise: rows row0+ty*8+i, cols tx*8+j ----
    float c = g_c, sc = g_sqrtc, bb = g_bb;
    float bh[8];
    *(float4*)(bh) = *(const float4*)(g_bhyp + tx * 8);
    *(float4*)(bh + 4) = *(const float4*)(g_bhyp + tx * 8 + 4);

#pragma unroll
    for (int i = 0; i < 8; i++) {
        int gr = row0 + ty * 8 + i;
        float zz = 0.f, zb = 0.f;
#pragma unroll
        for (int j = 0; j < 8; j++) {
            zz = fmaf(acc[i][j], acc[i][j], zz);
            zb = fmaf(acc[i][j], bh[j], zb);
        }
        zz = warp_sum(zz);
        zb = warp_sum(zb);

        float n1 = fmaxf(sqrtf(zz), EPSF);
        float tt = tanhf(sc * n1) / (sc * n1);  // z_hyp = tt * z
        float aa = tt * tt * zz;                // ||z_hyp||^2
        float ab = tt * zb;                     // <z_hyp, b_hyp>

        float common = 1.f + 2.f * c * ab;
        float den = fmaxf(common + c * c * aa * bb, EPSF);
        float ca = (common + c * bb) * tt / den;  // coeff on z
        float cb = (1.f - c * aa) / den;          // coeff on b_hyp

        float h[8];
        float hh = 0.f;
#pragma unroll
        for (int j = 0; j < 8; j++) {
            h[j] = fmaf(ca, acc[i][j], cb * bh[j]);
            hh = fmaf(h[j], h[j], hh);
        }
        hh = warp_sum(hh);

        float nh = fmaxf(sqrtf(hh), EPSF);
        float maxn = (1.f - EPSF) / sc;
        float s = (nh > maxn) ? (maxn / nh) : 1.f;  // projection scale
        float n2 = fmaxf(nh * s, EPSF);
        float arg = fminf(sc * n2, 1.f - EPSF);
        float f = s * atanhf(arg) / (sc * n2);

        if (gr < M) {
            float* hp = g_htan + (size_t)gr * 256 + tx * 8;
            *(float4*)(hp) =
                make_float4(f * h[0], f * h[1], f * h[2], f * h[3]);
            *(float4*)(hp + 4) =
                make_float4(f * h[4], f * h[5], f * h[6], f * h[7]);
        }
    }
}

// ---------------- SpMM + ReLU (warp per row, lane owns 8 cols) --------------
__global__ void __launch_bounds__(256)
spmm_kernel(float* __restrict__ out, int n) {
    int warp = (blockIdx.x * blockDim.x + threadIdx.x) >> 5;
    int lane = threadIdx.x & 31;
    if (warp >= n) return;
    int start = g_rowptr[warp];
    int end = g_rowptr[warp + 1];

    float4 a0 = make_float4(0.f, 0.f, 0.f, 0.f);
    float4 a1 = make_float4(0.f, 0.f, 0.f, 0.f);

    for (int e0 = start; e0 < end; e0 += 32) {
        int e = e0 + lane;
        int cc = 0;
        float vv = 0.f;
        if (e < end) {
            cc = g_scols[e];
            vv = g_svals[e];
        }
        int m = min(32, end - e0);
#pragma unroll 4
        for (int j = 0; j < m; j++) {
            int cj = __shfl_sync(0xffffffffu, cc, j);
            float vj = __shfl_sync(0xffffffffu, vv, j);
            const float4* hp =
                (const float4*)(g_htan + (size_t)cj * 256 + lane * 8);
            float4 h0 = __ldg(hp);
            float4 h1 = __ldg(hp + 1);
            a0.x = fmaf(vj, h0.x, a0.x);
            a0.y = fmaf(vj, h0.y, a0.y);
            a0.z = fmaf(vj, h0.z, a0.z);
            a0.w = fmaf(vj, h0.w, a0.w);
            a1.x = fmaf(vj, h1.x, a1.x);
            a1.y = fmaf(vj, h1.y, a1.y);
            a1.z = fmaf(vj, h1.z, a1.z);
            a1.w = fmaf(vj, h1.w, a1.w);
        }
    }
    a0.x = fmaxf(a0.x, 0.f); a0.y = fmaxf(a0.y, 0.f);
    a0.z = fmaxf(a0.z, 0.f); a0.w = fmaxf(a0.w, 0.f);
    a1.x = fmaxf(a1.x, 0.f); a1.y = fmaxf(a1.y, 0.f);
    a1.z = fmaxf(a1.z, 0.f); a1.w = fmaxf(a1.w, 0.f);
    float4* op = (float4*)(out + (size_t)warp * 256 + lane * 8);
    op[0] = a0;
    op[1] = a1;
}

// ---------------- launch -----------------------------------------------------
extern "C" void kernel_launch(void* const* d_in, const int* in_sizes, int n_in,
                              void* d_out, int out_size) {
    const float* x      = (const float*)d_in[0];
    const int*   arows  = (const int*)d_in[1];
    const int*   acols  = (const int*)d_in[2];
    const float* avals  = (const float*)d_in[3];
    const float* W      = (const float*)d_in[4];
    const float* bias   = (const float*)d_in[5];
    const float* ctheta = (const float*)d_in[6];
    float* out = (float*)d_out;

    int M = in_sizes[0] / D;
    int E = in_sizes[1];
    if (M > NN) M = NN;
    if (E > NE) E = NE;

    int nb = (M + SCAN_B - 1) / SCAN_B;

    prep_kernel<<<1, D>>>(bias, ctheta);
    zero_cnt_kernel<<<(M + 255) / 256, 256>>>(M);
    hist_kernel<<<(E + 255) / 256, 256>>>(arows, E);
    scan_block_kernel<<<nb, SCAN_B>>>(M);
    scan_bsum_kernel<<<1, 128>>>(nb);
    scan_add_kernel<<<(M + 255) / 256, 256>>>(M);
    scatter_kernel<<<(E + 255) / 256, 256>>>(arows, acols, avals, E);
    gemm_fused_kernel<<<(M + 63) / 64, 256>>>(x, W, M);
    spmm_kernel<<<(M + 7) / 8, 256>>>(out, M);
}